// round 14
// baseline (speedup 1.0000x reference)
#include <cuda_runtime.h>
#include <cuda_bf16.h>
#include <cstdint>

// Problem constants
#define BB    4
#define SS    4096
#define DD    1024
#define MM    (BB * SS)      // 16384
#define NN    (2 * DD)       // 2048
#define KK    DD             // 1024

#define NCHUNK 256
#define CLEN   (SS / NCHUNK) // 16
#define NCH    (BB * DD)     // 4096 channels

// Scratch (static device globals)
// g_cv holds interleaved (c,v) pairs: row m, cols [2d, 2d+1] = (c_d, v_d).
__device__ float g_cv[(size_t)MM * NN];          // 128 MiB
// Chunk transforms in [channel][chunk] layout (coalesced for passB).
__device__ float g_chunkC[NCH * NCHUNK];
__device__ float g_chunkV[NCH * NCHUNK];
__device__ float g_h0[NCHUNK * NCH];             // [chunk][channel] (passC-coalesced)
__device__ __align__(16) __nv_bfloat16 g_Ahi[(size_t)MM * KK];  // 32 MiB
__device__ __align__(16) __nv_bfloat16 g_Alo[(size_t)MM * KK];
__device__ __align__(16) __nv_bfloat16 g_Bhi[(size_t)NN * KK];  // 4 MiB (row-permuted W)
__device__ __align__(16) __nv_bfloat16 g_Blo[(size_t)NN * KK];

// ===========================================================================
// bf16 split helpers
// ===========================================================================
__device__ __forceinline__ uint32_t f2bf_bits(float x) {
    uint32_t u = __float_as_uint(x);
    return (u + 0x7FFFu + ((u >> 16) & 1u)) >> 16;
}
__device__ __forceinline__ float bf2f(uint32_t b) {
    return __uint_as_float(b << 16);
}
__device__ __forceinline__ void split4(float4 v, uint2& hi, uint2& lo) {
    uint32_t h0 = f2bf_bits(v.x), h1 = f2bf_bits(v.y);
    uint32_t h2 = f2bf_bits(v.z), h3 = f2bf_bits(v.w);
    float l0 = v.x - bf2f(h0), l1 = v.y - bf2f(h1);
    float l2 = v.z - bf2f(h2), l3 = v.w - bf2f(h3);
    uint32_t a0 = f2bf_bits(l0), a1 = f2bf_bits(l1);
    uint32_t a2 = f2bf_bits(l2), a3 = f2bf_bits(l3);
    hi = make_uint2(h0 | (h1 << 16), h2 | (h3 << 16));
    lo = make_uint2(a0 | (a1 << 16), a2 | (a3 << 16));
}

// ===========================================================================
// Convert: x -> (Ahi, Alo); W -> row-permuted (Bhi, Blo).
// Permutation: W row e -> 2e (hidden ch e) ; row e>=1024 -> 2(e-1024)+1 (gate).
// ===========================================================================
#define A8 ((size_t)MM * KK / 8)   // 2097152
#define B8 ((size_t)NN * KK / 8)   // 262144

__global__ __launch_bounds__(256)
void convert_kernel(const float* __restrict__ x, const float* __restrict__ W)
{
    const size_t i = (size_t)blockIdx.x * 256 + threadIdx.x;
    if (i < A8) {
        const float4 v0 = ((const float4*)x)[i * 2];
        const float4 v1 = ((const float4*)x)[i * 2 + 1];
        uint2 h0, l0, h1, l1;
        split4(v0, h0, l0);
        split4(v1, h1, l1);
        ((uint4*)g_Ahi)[i] = make_uint4(h0.x, h0.y, h1.x, h1.y);
        ((uint4*)g_Alo)[i] = make_uint4(l0.x, l0.y, l1.x, l1.y);
    } else if (i < A8 + B8) {
        const size_t j = i - A8;
        const size_t el = j * 8;
        const int e = (int)(el >> 10);
        const int col = (int)(el & 1023);
        const int p = (e < DD) ? (2 * e) : (2 * (e - DD) + 1);
        const float4 v0 = ((const float4*)W)[j * 2];
        const float4 v1 = ((const float4*)W)[j * 2 + 1];
        uint2 h0, l0, h1, l1;
        split4(v0, h0, l0);
        split4(v1, h1, l1);
        const size_t dst = ((size_t)p * KK + col) / 8;
        ((uint4*)g_Bhi)[dst] = make_uint4(h0.x, h0.y, h1.x, h1.y);
        ((uint4*)g_Blo)[dst] = make_uint4(l0.x, l0.y, l1.x, l1.y);
    }
}

// ===========================================================================
// c = sigmoid(-gate), v = sigmoid(gate)*g(hidden)
// ===========================================================================
__device__ __forceinline__ void compute_cv(float hidden, float gate,
                                           float& c, float& v)
{
    const float eg = __expf(gate);
    c = 1.f / (1.f + eg);
    const float z = 1.f - c;
    float gg;
    if (hidden >= 0.f) gg = hidden + 0.5f;
    else               gg = 1.f / (1.f + __expf(-hidden));
    v = z * gg;
}

// ===========================================================================
// GEMM: hg = [Ahi|Ahi|Alo] * [Bhi|Blo|Bhi]^T over virtual K = 3072 bf16.
// CTA 128x128, BK=64, 3-stage cp.async, ldmatrix, 8 warps, 2 CTAs/SM.
// Epilogue: compute (c,v), write g_cv, AND compose per-16-step chunk
// transforms in smem (fused scan_passA).
// ===========================================================================
#define TM 128
#define TN 128
#define BKB 64
#define KCHUNKS 48                 // 3 segments x 16 chunks
#define AST 16384
#define STAGE_B 32768
#define GEMM_SMEM (3 * STAGE_B)    // 98304

// Epilogue smem layout (aliases pipeline stages): per channel column of
// 128 rows x (c,v) float2, pitch 258 floats for bank spread.
#define CH_PITCH 258
// 64 * 258 * 4 = 66048 bytes <= 98304 OK

#define CP_ASYNC16(dst, src) \
    asm volatile("cp.async.cg.shared.global [%0], [%1], 16;" \
                 :: "r"(dst), "l"(src))
#define CP_COMMIT() asm volatile("cp.async.commit_group;")
#define CP_WAIT1()  asm volatile("cp.async.wait_group 1;")
#define CP_WAIT0()  asm volatile("cp.async.wait_group 0;")
#define LDSM4(r0, r1, r2, r3, addr) \
    asm volatile("ldmatrix.sync.aligned.m8n8.x4.shared.b16 {%0,%1,%2,%3}, [%4];" \
                 : "=r"(r0), "=r"(r1), "=r"(r2), "=r"(r3) : "r"(addr))

__device__ __forceinline__ uint32_t smem_u32(const void* p) {
    uint32_t a;
    asm("{ .reg .u64 t; cvta.to.shared.u64 t, %1; cvt.u32.u64 %0, t; }"
        : "=r"(a) : "l"(p));
    return a;
}

__device__ __forceinline__ void mma_bf16(float& d0, float& d1, float& d2, float& d3,
                                         uint32_t a0, uint32_t a1, uint32_t a2, uint32_t a3,
                                         uint32_t b0, uint32_t b1)
{
    asm volatile(
        "mma.sync.aligned.m16n8k16.row.col.f32.bf16.bf16.f32 "
        "{%0,%1,%2,%3}, {%4,%5,%6,%7}, {%8,%9}, {%0,%1,%2,%3};"
        : "+f"(d0), "+f"(d1), "+f"(d2), "+f"(d3)
        : "r"(a0), "r"(a1), "r"(a2), "r"(a3), "r"(b0), "r"(b1));
}

struct ChunkSrc {
    const __nv_bfloat16* a;
    const __nv_bfloat16* b;
    int kk;
};
__device__ __forceinline__ ChunkSrc chunk_src(int kc) {
    ChunkSrc s;
    const int seg = kc >> 4;
    s.kk = (kc & 15) * BKB;
    s.a = (seg < 2) ? g_Ahi : g_Alo;
    s.b = (seg == 1) ? g_Blo : g_Bhi;
    return s;
}

__global__ __launch_bounds__(256, 2)
void mingru_gemm()
{
    extern __shared__ char smem[];
    const uint32_t sb = smem_u32(smem);
    const int tid = threadIdx.x;
    const int wid = tid >> 5, lid = tid & 31;
    const int m0 = blockIdx.y * TM, n0 = blockIdx.x * TN;

    const int crow0 = tid >> 3;
    const int cuc   = tid & 7;
    const uint32_t cdst0 = (uint32_t)(crow0 * 128 + ((cuc * 16) ^ ((crow0 & 7) << 4)));

    const int rr = lid & 7, q = lid >> 3;
    const int arow = (q & 1) * 8 + rr;
    const uint32_t acb = (uint32_t)((q >> 1) * 16);
    const int brow = (q >> 1) * 8 + rr;
    const uint32_t bcb = (uint32_t)((q & 1) * 16);
    const uint32_t lxr = (uint32_t)(rr << 4);

    const int wm = (wid >> 2) * 64;
    const int wn = (wid & 3) * 32;
    const int gg = lid >> 2;
    const int t4 = lid & 3;

    float acc[4][4][4];
#pragma unroll
    for (int i = 0; i < 4; i++)
#pragma unroll
        for (int j = 0; j < 4; j++)
#pragma unroll
            for (int e = 0; e < 4; e++) acc[i][j][e] = 0.f;

    auto issue = [&](int kc, int s) {
        const ChunkSrc cs = chunk_src(kc);
        const uint32_t As = sb + s * STAGE_B;
        const uint32_t Bs = As + AST;
#pragma unroll
        for (int i = 0; i < 4; i++) {
            const int row = crow0 + i * 32;
            const uint32_t d = cdst0 + i * 4096;
            CP_ASYNC16(As + d, cs.a + (size_t)(m0 + row) * KK + cs.kk + cuc * 8);
            CP_ASYNC16(Bs + d, cs.b + (size_t)(n0 + row) * KK + cs.kk + cuc * 8);
        }
        CP_COMMIT();
    };

    issue(0, 0);
    issue(1, 1);

    for (int kc = 0; kc < KCHUNKS; kc++) {
        if (kc == KCHUNKS - 1) { CP_WAIT0(); } else { CP_WAIT1(); }
        __syncthreads();

        if (kc + 2 < KCHUNKS) issue(kc + 2, (kc + 2) % 3);

        const uint32_t As = sb + (kc % 3) * STAGE_B;
        const uint32_t Bs = As + AST;

#pragma unroll
        for (int kt = 0; kt < 4; kt++) {
            uint32_t af[4][4];
#pragma unroll
            for (int i = 0; i < 4; i++) {
                const uint32_t addr = As + (uint32_t)((wm + i * 16 + arow) * 128)
                                    + (((uint32_t)(kt * 32) + acb) ^ lxr);
                LDSM4(af[i][0], af[i][1], af[i][2], af[i][3], addr);
            }
            uint32_t bf[4][2];
            {
                const uint32_t addr0 = Bs + (uint32_t)((wn + brow) * 128)
                                     + (((uint32_t)(kt * 32) + bcb) ^ lxr);
                LDSM4(bf[0][0], bf[0][1], bf[1][0], bf[1][1], addr0);
                LDSM4(bf[2][0], bf[2][1], bf[3][0], bf[3][1], addr0 + 16 * 128);
            }
#pragma unroll
            for (int i = 0; i < 4; i++)
#pragma unroll
                for (int j = 0; j < 4; j++)
                    mma_bf16(acc[i][j][0], acc[i][j][1], acc[i][j][2], acc[i][j][3],
                             af[i][0], af[i][1], af[i][2], af[i][3],
                             bf[j][0], bf[j][1]);
        }
    }

    // Make sure all warps are done reading pipeline smem before aliasing it.
    __syncthreads();
    float* scv = (float*)smem;   // [64 channels][CH_PITCH floats]

    // Epilogue: (c,v) per accumulator pair -> global g_cv + smem tile.
#pragma unroll
    for (int i = 0; i < 4; i++) {
        const int rl0 = wm + i * 16 + gg;          // local row (timestep in tile)
        const int r0 = m0 + rl0;
#pragma unroll
        for (int j = 0; j < 4; j++) {
            const int c = wn + j * 8 + t4 * 2;     // local g_cv col (even)
            const int ch_local = c >> 1;           // 0..63
            float cv0, vv0, cv1, vv1;
            compute_cv(acc[i][j][0], acc[i][j][1], cv0, vv0);
            compute_cv(acc[i][j][2], acc[i][j][3], cv1, vv1);
            *(float2*)(g_cv + (size_t)r0 * NN + n0 + c)       = make_float2(cv0, vv0);
            *(float2*)(g_cv + (size_t)(r0 + 8) * NN + n0 + c) = make_float2(cv1, vv1);
            *(float2*)&scv[ch_local * CH_PITCH + rl0 * 2]       = make_float2(cv0, vv0);
            *(float2*)&scv[ch_local * CH_PITCH + (rl0 + 8) * 2] = make_float2(cv1, vv1);
        }
    }
    __syncthreads();

    // Fused scan_passA: compose 8 sub-chunks of 16 timesteps x 64 channels.
    // Output layout: [channel][chunk] (coalesced for passB).
    {
        const int sc = tid >> 5;
        const int l  = tid & 31;
        const int ch0 = 2 * l;
        float C0 = 1.f, V0 = 0.f, C1 = 1.f, V1 = 0.f;
        const float* p0 = &scv[ch0 * CH_PITCH + sc * 32];
        const float* p1 = p0 + CH_PITCH;
#pragma unroll
        for (int r = 0; r < 16; r++) {
            const float c0 = p0[r * 2], v0 = p0[r * 2 + 1];
            const float c1 = p1[r * 2], v1 = p1[r * 2 + 1];
            V0 = fmaf(c0, V0, v0);  C0 *= c0;
            V1 = fmaf(c1, V1, v1);  C1 *= c1;
        }
        const int b = blockIdx.y >> 5;                      // batch
        const int k = ((blockIdx.y & 31) << 3) + sc;        // global chunk 0..255
        const int chg = b * DD + (n0 >> 1) + ch0;           // global channel
        g_chunkC[(size_t)chg * NCHUNK + k]       = C0;
        g_chunkC[(size_t)(chg + 1) * NCHUNK + k] = C1;
        g_chunkV[(size_t)chg * NCHUNK + k]       = V0;
        g_chunkV[(size_t)(chg + 1) * NCHUNK + k] = V1;
    }
}

// ===========================================================================
// passB: warp-per-channel associative scan over the 256 chunk transforms.
// [ch][k] layout: lane l loads chunks [8l, 8l+8) = two float4s, coalesced.
// ===========================================================================
#define KPL (NCHUNK / 32)   // 8 chunks per lane
__global__ __launch_bounds__(256)
void scan_passB()
{
    const int warp = (blockIdx.x * 256 + threadIdx.x) >> 5;  // 0..4095 == ch
    const int lane = threadIdx.x & 31;
    const int ch = warp;

    const float4* pc = (const float4*)&g_chunkC[(size_t)ch * NCHUNK + lane * KPL];
    const float4* pv = (const float4*)&g_chunkV[(size_t)ch * NCHUNK + lane * KPL];
    const float4 c40 = pc[0], c41 = pc[1];
    const float4 v40 = pv[0], v41 = pv[1];
    const float c8[KPL] = {c40.x, c40.y, c40.z, c40.w, c41.x, c41.y, c41.z, c41.w};
    const float v8[KPL] = {v40.x, v40.y, v40.z, v40.w, v41.x, v41.y, v41.z, v41.w};

    float C = c8[0], V = v8[0];
#pragma unroll
    for (int j = 1; j < KPL; j++) {
        V = fmaf(c8[j], V, v8[j]);
        C *= c8[j];
    }
#pragma unroll
    for (int off = 1; off < 32; off <<= 1) {
        const float Cp = __shfl_up_sync(0xFFFFFFFFu, C, off);
        const float Vp = __shfl_up_sync(0xFFFFFFFFu, V, off);
        if (lane >= off) {
            V = fmaf(C, Vp, V);
            C *= Cp;
        }
    }
    const float Vprev = __shfl_up_sync(0xFFFFFFFFu, V, 1);
    float h = (lane == 0) ? 0.f : Vprev;
#pragma unroll
    for (int j = 0; j < KPL; j++) {
        const int k = lane * KPL + j;
        g_h0[k * NCH + ch] = h;              // [k][ch] for passC coalescing
        h = fmaf(c8[j], h, v8[j]);
    }
}

// ===========================================================================
// passC: replay within chunk from h0, write output.
// ===========================================================================
__global__ __launch_bounds__(256)
void scan_passC(float* __restrict__ out)
{
    const int t = threadIdx.x;
    const int k = blockIdx.x;
    const int b = blockIdx.y;
    const size_t base = ((size_t)b * SS + (size_t)k * CLEN) * NN + t * 8;
    const float4* p0 = (const float4*)(g_cv + base);

    const int ch = b * DD + t * 4;
    const float4 h0v = *(const float4*)&g_h0[k * NCH + ch];
    float h[4] = {h0v.x, h0v.y, h0v.z, h0v.w};

    float4* po = (float4*)(out + ((size_t)b * SS + (size_t)k * CLEN) * DD + t * 4);
#pragma unroll 8
    for (int s = 0; s < CLEN; s++) {
        const float4 a = p0[s * (NN / 4)];
        const float4 bq = p0[s * (NN / 4) + 1];
        h[0] = fmaf(a.x, h[0], a.y);
        h[1] = fmaf(a.z, h[1], a.w);
        h[2] = fmaf(bq.x, h[2], bq.y);
        h[3] = fmaf(bq.z, h[3], bq.w);
        po[s * (DD / 4)] = make_float4(h[0], h[1], h[2], h[3]);
    }
}

// ===========================================================================
extern "C" void kernel_launch(void* const* d_in, const int* in_sizes, int n_in,
                              void* d_out, int out_size)
{
    const float* x = (const float*)d_in[0];   // [B, S, D]
    const float* W = (const float*)d_in[1];   // [2D, D]
    float* out = (float*)d_out;

    cudaFuncSetAttribute(mingru_gemm,
                         cudaFuncAttributeMaxDynamicSharedMemorySize, GEMM_SMEM);

    convert_kernel<<<(unsigned)((A8 + B8 + 255) / 256), 256>>>(x, W);

    dim3 ggrid(NN / TN, MM / TM);            // (16, 128)
    mingru_gemm<<<ggrid, 256, GEMM_SMEM>>>();

    scan_passB<<<(NCH * 32) / 256, 256>>>();

    dim3 sgrid(NCHUNK, BB);                  // (256, 4)
    scan_passC<<<sgrid, 256>>>(out);
}

// round 15
// speedup vs baseline: 1.5251x; 1.5251x over previous
#include <cuda_runtime.h>
#include <cuda_bf16.h>
#include <cstdint>

// Problem constants
#define BB    4
#define SS    4096
#define DD    1024
#define MM    (BB * SS)      // 16384
#define NN    (2 * DD)       // 2048
#define KK    DD             // 1024

#define NCHUNK 256
#define CLEN   (SS / NCHUNK) // 16
#define NCH    (BB * DD)     // 4096 channels

// Scratch (static device globals)
// g_cv holds interleaved (c,v) pairs: row m, cols [2d, 2d+1] = (c_d, v_d).
__device__ float g_cv[(size_t)MM * NN];          // 128 MiB
// Chunk transforms in [chunk][channel] layout (coalesced GEMM-epilogue writes).
__device__ float g_chunkC[NCHUNK * NCH];
__device__ float g_chunkV[NCHUNK * NCH];
__device__ float g_h0[NCHUNK * NCH];             // [chunk][channel] (passC-coalesced)
__device__ __align__(16) __nv_bfloat16 g_Ahi[(size_t)MM * KK];  // 32 MiB
__device__ __align__(16) __nv_bfloat16 g_Alo[(size_t)MM * KK];
__device__ __align__(16) __nv_bfloat16 g_Bhi[(size_t)NN * KK];  // 4 MiB (row-permuted W)
__device__ __align__(16) __nv_bfloat16 g_Blo[(size_t)NN * KK];

// ===========================================================================
// bf16 split helpers
// ===========================================================================
__device__ __forceinline__ uint32_t f2bf_bits(float x) {
    uint32_t u = __float_as_uint(x);
    return (u + 0x7FFFu + ((u >> 16) & 1u)) >> 16;
}
__device__ __forceinline__ float bf2f(uint32_t b) {
    return __uint_as_float(b << 16);
}
__device__ __forceinline__ void split4(float4 v, uint2& hi, uint2& lo) {
    uint32_t h0 = f2bf_bits(v.x), h1 = f2bf_bits(v.y);
    uint32_t h2 = f2bf_bits(v.z), h3 = f2bf_bits(v.w);
    float l0 = v.x - bf2f(h0), l1 = v.y - bf2f(h1);
    float l2 = v.z - bf2f(h2), l3 = v.w - bf2f(h3);
    uint32_t a0 = f2bf_bits(l0), a1 = f2bf_bits(l1);
    uint32_t a2 = f2bf_bits(l2), a3 = f2bf_bits(l3);
    hi = make_uint2(h0 | (h1 << 16), h2 | (h3 << 16));
    lo = make_uint2(a0 | (a1 << 16), a2 | (a3 << 16));
}

// ===========================================================================
// Convert: x -> (Ahi, Alo); W -> row-permuted (Bhi, Blo).
// Permutation: W row e -> 2e (hidden ch e) ; row e>=1024 -> 2(e-1024)+1 (gate).
// ===========================================================================
#define A8 ((size_t)MM * KK / 8)   // 2097152
#define B8 ((size_t)NN * KK / 8)   // 262144

__global__ __launch_bounds__(256)
void convert_kernel(const float* __restrict__ x, const float* __restrict__ W)
{
    const size_t i = (size_t)blockIdx.x * 256 + threadIdx.x;
    if (i < A8) {
        const float4 v0 = ((const float4*)x)[i * 2];
        const float4 v1 = ((const float4*)x)[i * 2 + 1];
        uint2 h0, l0, h1, l1;
        split4(v0, h0, l0);
        split4(v1, h1, l1);
        ((uint4*)g_Ahi)[i] = make_uint4(h0.x, h0.y, h1.x, h1.y);
        ((uint4*)g_Alo)[i] = make_uint4(l0.x, l0.y, l1.x, l1.y);
    } else if (i < A8 + B8) {
        const size_t j = i - A8;
        const size_t el = j * 8;
        const int e = (int)(el >> 10);
        const int col = (int)(el & 1023);
        const int p = (e < DD) ? (2 * e) : (2 * (e - DD) + 1);
        const float4 v0 = ((const float4*)W)[j * 2];
        const float4 v1 = ((const float4*)W)[j * 2 + 1];
        uint2 h0, l0, h1, l1;
        split4(v0, h0, l0);
        split4(v1, h1, l1);
        const size_t dst = ((size_t)p * KK + col) / 8;
        ((uint4*)g_Bhi)[dst] = make_uint4(h0.x, h0.y, h1.x, h1.y);
        ((uint4*)g_Blo)[dst] = make_uint4(l0.x, l0.y, l1.x, l1.y);
    }
}

// ===========================================================================
// c = sigmoid(-gate), v = sigmoid(gate)*g(hidden)
// ===========================================================================
__device__ __forceinline__ void compute_cv(float hidden, float gate,
                                           float& c, float& v)
{
    const float eg = __expf(gate);
    c = 1.f / (1.f + eg);
    const float z = 1.f - c;
    float gg;
    if (hidden >= 0.f) gg = hidden + 0.5f;
    else               gg = 1.f / (1.f + __expf(-hidden));
    v = z * gg;
}

// ===========================================================================
// GEMM: hg = [Ahi|Ahi|Alo] * [Bhi|Blo|Bhi]^T over virtual K = 3072 bf16.
// CTA 128x128, BK=64, 3-stage cp.async, ldmatrix, 8 warps, 2 CTAs/SM.
// Epilogue: compute (c,v), write g_cv, AND compose per-16-step chunk
// transforms in smem (fused scan_passA). All global stores coalesced.
// ===========================================================================
#define TM 128
#define TN 128
#define BKB 64
#define KCHUNKS 48                 // 3 segments x 16 chunks
#define AST 16384
#define STAGE_B 32768
#define GEMM_SMEM (3 * STAGE_B)    // 98304

// Epilogue smem layout (aliases pipeline stages): per channel column of
// 128 rows x (c,v) float2, pitch 258 floats for bank spread.
#define CH_PITCH 258
// 64 * 258 * 4 = 66048 bytes <= 98304 OK

#define CP_ASYNC16(dst, src) \
    asm volatile("cp.async.cg.shared.global [%0], [%1], 16;" \
                 :: "r"(dst), "l"(src))
#define CP_COMMIT() asm volatile("cp.async.commit_group;")
#define CP_WAIT1()  asm volatile("cp.async.wait_group 1;")
#define CP_WAIT0()  asm volatile("cp.async.wait_group 0;")
#define LDSM4(r0, r1, r2, r3, addr) \
    asm volatile("ldmatrix.sync.aligned.m8n8.x4.shared.b16 {%0,%1,%2,%3}, [%4];" \
                 : "=r"(r0), "=r"(r1), "=r"(r2), "=r"(r3) : "r"(addr))

__device__ __forceinline__ uint32_t smem_u32(const void* p) {
    uint32_t a;
    asm("{ .reg .u64 t; cvta.to.shared.u64 t, %1; cvt.u32.u64 %0, t; }"
        : "=r"(a) : "l"(p));
    return a;
}

__device__ __forceinline__ void mma_bf16(float& d0, float& d1, float& d2, float& d3,
                                         uint32_t a0, uint32_t a1, uint32_t a2, uint32_t a3,
                                         uint32_t b0, uint32_t b1)
{
    asm volatile(
        "mma.sync.aligned.m16n8k16.row.col.f32.bf16.bf16.f32 "
        "{%0,%1,%2,%3}, {%4,%5,%6,%7}, {%8,%9}, {%0,%1,%2,%3};"
        : "+f"(d0), "+f"(d1), "+f"(d2), "+f"(d3)
        : "r"(a0), "r"(a1), "r"(a2), "r"(a3), "r"(b0), "r"(b1));
}

struct ChunkSrc {
    const __nv_bfloat16* a;
    const __nv_bfloat16* b;
    int kk;
};
__device__ __forceinline__ ChunkSrc chunk_src(int kc) {
    ChunkSrc s;
    const int seg = kc >> 4;
    s.kk = (kc & 15) * BKB;
    s.a = (seg < 2) ? g_Ahi : g_Alo;
    s.b = (seg == 1) ? g_Blo : g_Bhi;
    return s;
}

__global__ __launch_bounds__(256, 2)
void mingru_gemm()
{
    extern __shared__ char smem[];
    const uint32_t sb = smem_u32(smem);
    const int tid = threadIdx.x;
    const int wid = tid >> 5, lid = tid & 31;
    const int m0 = blockIdx.y * TM, n0 = blockIdx.x * TN;

    const int crow0 = tid >> 3;
    const int cuc   = tid & 7;
    const uint32_t cdst0 = (uint32_t)(crow0 * 128 + ((cuc * 16) ^ ((crow0 & 7) << 4)));

    const int rr = lid & 7, q = lid >> 3;
    const int arow = (q & 1) * 8 + rr;
    const uint32_t acb = (uint32_t)((q >> 1) * 16);
    const int brow = (q >> 1) * 8 + rr;
    const uint32_t bcb = (uint32_t)((q & 1) * 16);
    const uint32_t lxr = (uint32_t)(rr << 4);

    const int wm = (wid >> 2) * 64;
    const int wn = (wid & 3) * 32;
    const int gg = lid >> 2;
    const int t4 = lid & 3;

    float acc[4][4][4];
#pragma unroll
    for (int i = 0; i < 4; i++)
#pragma unroll
        for (int j = 0; j < 4; j++)
#pragma unroll
            for (int e = 0; e < 4; e++) acc[i][j][e] = 0.f;

    auto issue = [&](int kc, int s) {
        const ChunkSrc cs = chunk_src(kc);
        const uint32_t As = sb + s * STAGE_B;
        const uint32_t Bs = As + AST;
#pragma unroll
        for (int i = 0; i < 4; i++) {
            const int row = crow0 + i * 32;
            const uint32_t d = cdst0 + i * 4096;
            CP_ASYNC16(As + d, cs.a + (size_t)(m0 + row) * KK + cs.kk + cuc * 8);
            CP_ASYNC16(Bs + d, cs.b + (size_t)(n0 + row) * KK + cs.kk + cuc * 8);
        }
        CP_COMMIT();
    };

    issue(0, 0);
    issue(1, 1);

    for (int kc = 0; kc < KCHUNKS; kc++) {
        if (kc == KCHUNKS - 1) { CP_WAIT0(); } else { CP_WAIT1(); }
        __syncthreads();

        if (kc + 2 < KCHUNKS) issue(kc + 2, (kc + 2) % 3);

        const uint32_t As = sb + (kc % 3) * STAGE_B;
        const uint32_t Bs = As + AST;

#pragma unroll
        for (int kt = 0; kt < 4; kt++) {
            uint32_t af[4][4];
#pragma unroll
            for (int i = 0; i < 4; i++) {
                const uint32_t addr = As + (uint32_t)((wm + i * 16 + arow) * 128)
                                    + (((uint32_t)(kt * 32) + acb) ^ lxr);
                LDSM4(af[i][0], af[i][1], af[i][2], af[i][3], addr);
            }
            uint32_t bf[4][2];
            {
                const uint32_t addr0 = Bs + (uint32_t)((wn + brow) * 128)
                                     + (((uint32_t)(kt * 32) + bcb) ^ lxr);
                LDSM4(bf[0][0], bf[0][1], bf[1][0], bf[1][1], addr0);
                LDSM4(bf[2][0], bf[2][1], bf[3][0], bf[3][1], addr0 + 16 * 128);
            }
#pragma unroll
            for (int i = 0; i < 4; i++)
#pragma unroll
                for (int j = 0; j < 4; j++)
                    mma_bf16(acc[i][j][0], acc[i][j][1], acc[i][j][2], acc[i][j][3],
                             af[i][0], af[i][1], af[i][2], af[i][3],
                             bf[j][0], bf[j][1]);
        }
    }

    // Make sure all warps are done reading pipeline smem before aliasing it.
    __syncthreads();
    float* scv = (float*)smem;   // [64 channels][CH_PITCH floats]

    // Epilogue: (c,v) per accumulator pair -> global g_cv + smem tile.
#pragma unroll
    for (int i = 0; i < 4; i++) {
        const int rl0 = wm + i * 16 + gg;          // local row (timestep in tile)
        const int r0 = m0 + rl0;
#pragma unroll
        for (int j = 0; j < 4; j++) {
            const int c = wn + j * 8 + t4 * 2;     // local g_cv col (even)
            const int ch_local = c >> 1;           // 0..63
            float cv0, vv0, cv1, vv1;
            compute_cv(acc[i][j][0], acc[i][j][1], cv0, vv0);
            compute_cv(acc[i][j][2], acc[i][j][3], cv1, vv1);
            *(float2*)(g_cv + (size_t)r0 * NN + n0 + c)       = make_float2(cv0, vv0);
            *(float2*)(g_cv + (size_t)(r0 + 8) * NN + n0 + c) = make_float2(cv1, vv1);
            *(float2*)&scv[ch_local * CH_PITCH + rl0 * 2]       = make_float2(cv0, vv0);
            *(float2*)&scv[ch_local * CH_PITCH + (rl0 + 8) * 2] = make_float2(cv1, vv1);
        }
    }
    __syncthreads();

    // Fused scan_passA: compose 8 sub-chunks of 16 timesteps x 64 channels.
    // Output layout: [chunk][channel] (coalesced float2 writes).
    {
        const int sc = tid >> 5;
        const int l  = tid & 31;
        const int ch0 = 2 * l;
        float C0 = 1.f, V0 = 0.f, C1 = 1.f, V1 = 0.f;
        const float* p0 = &scv[ch0 * CH_PITCH + sc * 32];
        const float* p1 = p0 + CH_PITCH;
#pragma unroll
        for (int r = 0; r < 16; r++) {
            const float c0 = p0[r * 2], v0 = p0[r * 2 + 1];
            const float c1 = p1[r * 2], v1 = p1[r * 2 + 1];
            V0 = fmaf(c0, V0, v0);  C0 *= c0;
            V1 = fmaf(c1, V1, v1);  C1 *= c1;
        }
        const int b = blockIdx.y >> 5;                      // batch
        const int k = ((blockIdx.y & 31) << 3) + sc;        // global chunk 0..255
        const int chg = b * DD + (n0 >> 1) + ch0;           // global channel
        *(float2*)&g_chunkC[k * NCH + chg] = make_float2(C0, C1);
        *(float2*)&g_chunkV[k * NCH + chg] = make_float2(V0, V1);
    }
}

// ===========================================================================
// passB: warp-per-channel associative scan over the 256 chunk transforms.
// smem-staged: gmem accesses sector-perfect, transpose lives in shared mem.
// CTA: 256 threads, 8 channels (8 warps, warp-per-channel). Grid 512.
// ===========================================================================
#define KPL (NCHUNK / 32)   // 8 chunks per lane
#define PB_CH 8
#define PB_PITCH 260        // floats per channel row in smem (bank spread)

__global__ __launch_bounds__(256)
void scan_passB()
{
    __shared__ float sC[PB_CH * PB_PITCH];
    __shared__ float sV[PB_CH * PB_PITCH];
    __shared__ float sH[PB_CH * PB_PITCH];

    const int tid = threadIdx.x;
    const int c0 = blockIdx.x * PB_CH;

    // Coalesced load + transpose: idx = (k, c), c fastest -> 32B sectors full.
#pragma unroll
    for (int it = 0; it < 8; it++) {
        const int idx = it * 256 + tid;          // 0..2047
        const int k = idx >> 3, c = idx & 7;
        sC[c * PB_PITCH + k] = g_chunkC[k * NCH + c0 + c];
        sV[c * PB_PITCH + k] = g_chunkV[k * NCH + c0 + c];
    }
    __syncthreads();

    const int w = tid >> 5;       // channel within CTA
    const int lane = tid & 31;

    float c8[KPL], v8[KPL];
#pragma unroll
    for (int j = 0; j < KPL; j++) {
        c8[j] = sC[w * PB_PITCH + lane * KPL + j];
        v8[j] = sV[w * PB_PITCH + lane * KPL + j];
    }
    float C = c8[0], V = v8[0];
#pragma unroll
    for (int j = 1; j < KPL; j++) {
        V = fmaf(c8[j], V, v8[j]);
        C *= c8[j];
    }
#pragma unroll
    for (int off = 1; off < 32; off <<= 1) {
        const float Cp = __shfl_up_sync(0xFFFFFFFFu, C, off);
        const float Vp = __shfl_up_sync(0xFFFFFFFFu, V, off);
        if (lane >= off) {
            V = fmaf(C, Vp, V);
            C *= Cp;
        }
    }
    const float Vprev = __shfl_up_sync(0xFFFFFFFFu, V, 1);
    float h = (lane == 0) ? 0.f : Vprev;
#pragma unroll
    for (int j = 0; j < KPL; j++) {
        sH[w * PB_PITCH + lane * KPL + j] = h;
        h = fmaf(c8[j], h, v8[j]);
    }
    __syncthreads();

    // Coalesced store of h0 (transpose back out).
#pragma unroll
    for (int it = 0; it < 8; it++) {
        const int idx = it * 256 + tid;
        const int k = idx >> 3, c = idx & 7;
        g_h0[k * NCH + c0 + c] = sH[c * PB_PITCH + k];
    }
}

// ===========================================================================
// passC: replay within chunk from h0, write output.
// ===========================================================================
__global__ __launch_bounds__(256)
void scan_passC(float* __restrict__ out)
{
    const int t = threadIdx.x;
    const int k = blockIdx.x;
    const int b = blockIdx.y;
    const size_t base = ((size_t)b * SS + (size_t)k * CLEN) * NN + t * 8;
    const float4* p0 = (const float4*)(g_cv + base);

    const int ch = b * DD + t * 4;
    const float4 h0v = *(const float4*)&g_h0[k * NCH + ch];
    float h[4] = {h0v.x, h0v.y, h0v.z, h0v.w};

    float4* po = (float4*)(out + ((size_t)b * SS + (size_t)k * CLEN) * DD + t * 4);
#pragma unroll 8
    for (int s = 0; s < CLEN; s++) {
        const float4 a = p0[s * (NN / 4)];
        const float4 bq = p0[s * (NN / 4) + 1];
        h[0] = fmaf(a.x, h[0], a.y);
        h[1] = fmaf(a.z, h[1], a.w);
        h[2] = fmaf(bq.x, h[2], bq.y);
        h[3] = fmaf(bq.z, h[3], bq.w);
        po[s * (DD / 4)] = make_float4(h[0], h[1], h[2], h[3]);
    }
}

// ===========================================================================
extern "C" void kernel_launch(void* const* d_in, const int* in_sizes, int n_in,
                              void* d_out, int out_size)
{
    const float* x = (const float*)d_in[0];   // [B, S, D]
    const float* W = (const float*)d_in[1];   // [2D, D]
    float* out = (float*)d_out;

    cudaFuncSetAttribute(mingru_gemm,
                         cudaFuncAttributeMaxDynamicSharedMemorySize, GEMM_SMEM);

    convert_kernel<<<(unsigned)((A8 + B8 + 255) / 256), 256>>>(x, W);

    dim3 ggrid(NN / TN, MM / TM);            // (16, 128)
    mingru_gemm<<<ggrid, 256, GEMM_SMEM>>>();

    scan_passB<<<NCH / PB_CH, 256>>>();      // 512 CTAs, 8 channels each

    dim3 sgrid(NCHUNK, BB);                  // (256, 4)
    scan_passC<<<sgrid, 256>>>(out);
}

// round 16
// speedup vs baseline: 2.3056x; 1.5117x over previous
#include <cuda_runtime.h>
#include <cuda_fp16.h>
#include <cstdint>

// Problem constants
#define BB    4
#define SS    4096
#define DD    1024
#define MM    (BB * SS)      // 16384
#define NN    (2 * DD)       // 2048
#define KK    DD             // 1024

#define NCHUNK 256
#define CLEN   (SS / NCHUNK) // 16
#define NCH    (BB * DD)     // 4096 channels

// Scratch (static device globals)
// g_cv holds interleaved (c,v) pairs: row m, cols [2d, 2d+1] = (c_d, v_d).
__device__ float g_cv[(size_t)MM * NN];          // 128 MiB
// Chunk transforms in [chunk][channel] layout (coalesced GEMM-epilogue writes).
__device__ float g_chunkC[NCHUNK * NCH];
__device__ float g_chunkV[NCHUNK * NCH];
__device__ float g_h0[NCHUNK * NCH];             // [chunk][channel]
__device__ __align__(16) __half g_A[(size_t)MM * KK];  // 32 MiB fp16 x
__device__ __align__(16) __half g_B[(size_t)NN * KK];  // 4 MiB fp16 W (row-permuted)

// ===========================================================================
// Convert: x -> fp16 A; W -> fp16 row-permuted B.
// Permutation: W row e -> 2e (hidden ch e); row e>=1024 -> 2(e-1024)+1 (gate).
// 8 floats per thread, one STG.128 out.
// ===========================================================================
#define A8 ((size_t)MM * KK / 8)   // 2097152
#define B8 ((size_t)NN * KK / 8)   // 262144

__device__ __forceinline__ uint4 cvt8(float4 v0, float4 v1) {
    __half2 p0 = __floats2half2_rn(v0.x, v0.y);
    __half2 p1 = __floats2half2_rn(v0.z, v0.w);
    __half2 p2 = __floats2half2_rn(v1.x, v1.y);
    __half2 p3 = __floats2half2_rn(v1.z, v1.w);
    return make_uint4(*(uint32_t*)&p0, *(uint32_t*)&p1,
                      *(uint32_t*)&p2, *(uint32_t*)&p3);
}

__global__ __launch_bounds__(256)
void convert_kernel(const float* __restrict__ x, const float* __restrict__ W)
{
    const size_t i = (size_t)blockIdx.x * 256 + threadIdx.x;
    if (i < A8) {
        const float4 v0 = ((const float4*)x)[i * 2];
        const float4 v1 = ((const float4*)x)[i * 2 + 1];
        ((uint4*)g_A)[i] = cvt8(v0, v1);
    } else if (i < A8 + B8) {
        const size_t j = i - A8;
        const size_t el = j * 8;
        const int e = (int)(el >> 10);
        const int col = (int)(el & 1023);
        const int p = (e < DD) ? (2 * e) : (2 * (e - DD) + 1);
        const float4 v0 = ((const float4*)W)[j * 2];
        const float4 v1 = ((const float4*)W)[j * 2 + 1];
        ((uint4*)g_B)[((size_t)p * KK + col) / 8] = cvt8(v0, v1);
    }
}

// ===========================================================================
// c = sigmoid(-gate), v = sigmoid(gate)*g(hidden)
// ===========================================================================
__device__ __forceinline__ void compute_cv(float hidden, float gate,
                                           float& c, float& v)
{
    const float eg = __expf(gate);
    c = 1.f / (1.f + eg);
    const float z = 1.f - c;
    float gg;
    if (hidden >= 0.f) gg = hidden + 0.5f;
    else               gg = 1.f / (1.f + __expf(-hidden));
    v = z * gg;
}

// ===========================================================================
// GEMM: hg = A * B^T, fp16 inputs, fp32 accum. K = 1024.
// CTA 128x128, BK=64, 3-stage cp.async, ldmatrix, 8 warps, 2 CTAs/SM.
// Epilogue: compute (c,v), write g_cv, and compose per-16-step chunk
// transforms in smem (fused scan_passA). All global stores coalesced.
// ===========================================================================
#define TM 128
#define TN 128
#define BKB 64
#define KCHUNKS 16                 // 1024 / 64
#define AST 16384
#define STAGE_B 32768
#define GEMM_SMEM (3 * STAGE_B)    // 98304

#define CH_PITCH 258
// 64 * 258 * 4 = 66048 bytes <= 98304 OK

#define CP_ASYNC16(dst, src) \
    asm volatile("cp.async.cg.shared.global [%0], [%1], 16;" \
                 :: "r"(dst), "l"(src))
#define CP_COMMIT() asm volatile("cp.async.commit_group;")
#define CP_WAIT1()  asm volatile("cp.async.wait_group 1;")
#define CP_WAIT0()  asm volatile("cp.async.wait_group 0;")
#define LDSM4(r0, r1, r2, r3, addr) \
    asm volatile("ldmatrix.sync.aligned.m8n8.x4.shared.b16 {%0,%1,%2,%3}, [%4];" \
                 : "=r"(r0), "=r"(r1), "=r"(r2), "=r"(r3) : "r"(addr))

__device__ __forceinline__ uint32_t smem_u32(const void* p) {
    uint32_t a;
    asm("{ .reg .u64 t; cvta.to.shared.u64 t, %1; cvt.u32.u64 %0, t; }"
        : "=r"(a) : "l"(p));
    return a;
}

__device__ __forceinline__ void mma_f16(float& d0, float& d1, float& d2, float& d3,
                                        uint32_t a0, uint32_t a1, uint32_t a2, uint32_t a3,
                                        uint32_t b0, uint32_t b1)
{
    asm volatile(
        "mma.sync.aligned.m16n8k16.row.col.f32.f16.f16.f32 "
        "{%0,%1,%2,%3}, {%4,%5,%6,%7}, {%8,%9}, {%0,%1,%2,%3};"
        : "+f"(d0), "+f"(d1), "+f"(d2), "+f"(d3)
        : "r"(a0), "r"(a1), "r"(a2), "r"(a3), "r"(b0), "r"(b1));
}

__global__ __launch_bounds__(256, 2)
void mingru_gemm()
{
    extern __shared__ char smem[];
    const uint32_t sb = smem_u32(smem);
    const int tid = threadIdx.x;
    const int wid = tid >> 5, lid = tid & 31;
    const int m0 = blockIdx.y * TM, n0 = blockIdx.x * TN;

    const int crow0 = tid >> 3;
    const int cuc   = tid & 7;
    const uint32_t cdst0 = (uint32_t)(crow0 * 128 + ((cuc * 16) ^ ((crow0 & 7) << 4)));

    const int rr = lid & 7, q = lid >> 3;
    const int arow = (q & 1) * 8 + rr;
    const uint32_t acb = (uint32_t)((q >> 1) * 16);
    const int brow = (q >> 1) * 8 + rr;
    const uint32_t bcb = (uint32_t)((q & 1) * 16);
    const uint32_t lxr = (uint32_t)(rr << 4);

    const int wm = (wid >> 2) * 64;
    const int wn = (wid & 3) * 32;
    const int gg = lid >> 2;
    const int t4 = lid & 3;

    float acc[4][4][4];
#pragma unroll
    for (int i = 0; i < 4; i++)
#pragma unroll
        for (int j = 0; j < 4; j++)
#pragma unroll
            for (int e = 0; e < 4; e++) acc[i][j][e] = 0.f;

    auto issue = [&](int kc, int s) {
        const int kk = kc * BKB;
        const uint32_t As = sb + s * STAGE_B;
        const uint32_t Bs = As + AST;
#pragma unroll
        for (int i = 0; i < 4; i++) {
            const int row = crow0 + i * 32;
            const uint32_t d = cdst0 + i * 4096;
            CP_ASYNC16(As + d, g_A + (size_t)(m0 + row) * KK + kk + cuc * 8);
            CP_ASYNC16(Bs + d, g_B + (size_t)(n0 + row) * KK + kk + cuc * 8);
        }
        CP_COMMIT();
    };

    issue(0, 0);
    issue(1, 1);

    for (int kc = 0; kc < KCHUNKS; kc++) {
        if (kc == KCHUNKS - 1) { CP_WAIT0(); } else { CP_WAIT1(); }
        __syncthreads();

        if (kc + 2 < KCHUNKS) issue(kc + 2, (kc + 2) % 3);

        const uint32_t As = sb + (kc % 3) * STAGE_B;
        const uint32_t Bs = As + AST;

#pragma unroll
        for (int kt = 0; kt < 4; kt++) {
            uint32_t af[4][4];
#pragma unroll
            for (int i = 0; i < 4; i++) {
                const uint32_t addr = As + (uint32_t)((wm + i * 16 + arow) * 128)
                                    + (((uint32_t)(kt * 32) + acb) ^ lxr);
                LDSM4(af[i][0], af[i][1], af[i][2], af[i][3], addr);
            }
            uint32_t bf[4][2];
            {
                const uint32_t addr0 = Bs + (uint32_t)((wn + brow) * 128)
                                     + (((uint32_t)(kt * 32) + bcb) ^ lxr);
                LDSM4(bf[0][0], bf[0][1], bf[1][0], bf[1][1], addr0);
                LDSM4(bf[2][0], bf[2][1], bf[3][0], bf[3][1], addr0 + 16 * 128);
            }
#pragma unroll
            for (int i = 0; i < 4; i++)
#pragma unroll
                for (int j = 0; j < 4; j++)
                    mma_f16(acc[i][j][0], acc[i][j][1], acc[i][j][2], acc[i][j][3],
                            af[i][0], af[i][1], af[i][2], af[i][3],
                            bf[j][0], bf[j][1]);
        }
    }

    // All warps done with pipeline smem before aliasing it.
    __syncthreads();
    float* scv = (float*)smem;   // [64 channels][CH_PITCH floats]

    // Epilogue: (c,v) per accumulator pair -> global g_cv + smem tile.
#pragma unroll
    for (int i = 0; i < 4; i++) {
        const int rl0 = wm + i * 16 + gg;          // local row (timestep in tile)
        const int r0 = m0 + rl0;
#pragma unroll
        for (int j = 0; j < 4; j++) {
            const int c = wn + j * 8 + t4 * 2;     // local g_cv col (even)
            const int ch_local = c >> 1;           // 0..63
            float cv0, vv0, cv1, vv1;
            compute_cv(acc[i][j][0], acc[i][j][1], cv0, vv0);
            compute_cv(acc[i][j][2], acc[i][j][3], cv1, vv1);
            *(float2*)(g_cv + (size_t)r0 * NN + n0 + c)       = make_float2(cv0, vv0);
            *(float2*)(g_cv + (size_t)(r0 + 8) * NN + n0 + c) = make_float2(cv1, vv1);
            *(float2*)&scv[ch_local * CH_PITCH + rl0 * 2]       = make_float2(cv0, vv0);
            *(float2*)&scv[ch_local * CH_PITCH + (rl0 + 8) * 2] = make_float2(cv1, vv1);
        }
    }
    __syncthreads();

    // Fused scan_passA: compose 8 sub-chunks of 16 timesteps x 64 channels.
    // Output layout: [chunk][channel] (coalesced float2 writes).
    {
        const int sc = tid >> 5;
        const int l  = tid & 31;
        const int ch0 = 2 * l;
        float C0 = 1.f, V0 = 0.f, C1 = 1.f, V1 = 0.f;
        const float* p0 = &scv[ch0 * CH_PITCH + sc * 32];
        const float* p1 = p0 + CH_PITCH;
#pragma unroll
        for (int r = 0; r < 16; r++) {
            const float c0 = p0[r * 2], v0 = p0[r * 2 + 1];
            const float c1 = p1[r * 2], v1 = p1[r * 2 + 1];
            V0 = fmaf(c0, V0, v0);  C0 *= c0;
            V1 = fmaf(c1, V1, v1);  C1 *= c1;
        }
        const int b = blockIdx.y >> 5;                      // batch
        const int k = ((blockIdx.y & 31) << 3) + sc;        // global chunk 0..255
        const int chg = b * DD + (n0 >> 1) + ch0;           // global channel
        *(float2*)&g_chunkC[k * NCH + chg] = make_float2(C0, C1);
        *(float2*)&g_chunkV[k * NCH + chg] = make_float2(V0, V1);
    }
}

// ===========================================================================
// passB: warp-per-channel associative scan over the 256 chunk transforms.
// smem-staged: gmem accesses sector-perfect, transpose lives in shared mem.
// ===========================================================================
#define KPL (NCHUNK / 32)   // 8 chunks per lane
#define PB_CH 8
#define PB_PITCH 260

__global__ __launch_bounds__(256)
void scan_passB()
{
    __shared__ float sC[PB_CH * PB_PITCH];
    __shared__ float sV[PB_CH * PB_PITCH];
    __shared__ float sH[PB_CH * PB_PITCH];

    const int tid = threadIdx.x;
    const int c0 = blockIdx.x * PB_CH;

#pragma unroll
    for (int it = 0; it < 8; it++) {
        const int idx = it * 256 + tid;          // 0..2047
        const int k = idx >> 3, c = idx & 7;
        sC[c * PB_PITCH + k] = g_chunkC[k * NCH + c0 + c];
        sV[c * PB_PITCH + k] = g_chunkV[k * NCH + c0 + c];
    }
    __syncthreads();

    const int w = tid >> 5;
    const int lane = tid & 31;

    float c8[KPL], v8[KPL];
#pragma unroll
    for (int j = 0; j < KPL; j++) {
        c8[j] = sC[w * PB_PITCH + lane * KPL + j];
        v8[j] = sV[w * PB_PITCH + lane * KPL + j];
    }
    float C = c8[0], V = v8[0];
#pragma unroll
    for (int j = 1; j < KPL; j++) {
        V = fmaf(c8[j], V, v8[j]);
        C *= c8[j];
    }
#pragma unroll
    for (int off = 1; off < 32; off <<= 1) {
        const float Cp = __shfl_up_sync(0xFFFFFFFFu, C, off);
        const float Vp = __shfl_up_sync(0xFFFFFFFFu, V, off);
        if (lane >= off) {
            V = fmaf(C, Vp, V);
            C *= Cp;
        }
    }
    const float Vprev = __shfl_up_sync(0xFFFFFFFFu, V, 1);
    float h = (lane == 0) ? 0.f : Vprev;
#pragma unroll
    for (int j = 0; j < KPL; j++) {
        sH[w * PB_PITCH + lane * KPL + j] = h;
        h = fmaf(c8[j], h, v8[j]);
    }
    __syncthreads();

#pragma unroll
    for (int it = 0; it < 8; it++) {
        const int idx = it * 256 + tid;
        const int k = idx >> 3, c = idx & 7;
        g_h0[k * NCH + c0 + c] = sH[c * PB_PITCH + k];
    }
}

// ===========================================================================
// passC: replay within chunk from h0, write output.
// ===========================================================================
__global__ __launch_bounds__(256)
void scan_passC(float* __restrict__ out)
{
    const int t = threadIdx.x;
    const int k = blockIdx.x;
    const int b = blockIdx.y;
    const size_t base = ((size_t)b * SS + (size_t)k * CLEN) * NN + t * 8;
    const float4* p0 = (const float4*)(g_cv + base);

    const int ch = b * DD + t * 4;
    const float4 h0v = *(const float4*)&g_h0[k * NCH + ch];
    float h[4] = {h0v.x, h0v.y, h0v.z, h0v.w};

    float4* po = (float4*)(out + ((size_t)b * SS + (size_t)k * CLEN) * DD + t * 4);
#pragma unroll 8
    for (int s = 0; s < CLEN; s++) {
        const float4 a = p0[s * (NN / 4)];
        const float4 bq = p0[s * (NN / 4) + 1];
        h[0] = fmaf(a.x, h[0], a.y);
        h[1] = fmaf(a.z, h[1], a.w);
        h[2] = fmaf(bq.x, h[2], bq.y);
        h[3] = fmaf(bq.z, h[3], bq.w);
        po[s * (DD / 4)] = make_float4(h[0], h[1], h[2], h[3]);
    }
}

// ===========================================================================
extern "C" void kernel_launch(void* const* d_in, const int* in_sizes, int n_in,
                              void* d_out, int out_size)
{
    const float* x = (const float*)d_in[0];   // [B, S, D]
    const float* W = (const float*)d_in[1];   // [2D, D]
    float* out = (float*)d_out;

    cudaFuncSetAttribute(mingru_gemm,
                         cudaFuncAttributeMaxDynamicSharedMemorySize, GEMM_SMEM);

    convert_kernel<<<(unsigned)((A8 + B8 + 255) / 256), 256>>>(x, W);

    dim3 ggrid(NN / TN, MM / TM);            // (16, 128)
    mingru_gemm<<<ggrid, 256, GEMM_SMEM>>>();

    scan_passB<<<NCH / PB_CH, 256>>>();      // 512 CTAs, 8 channels each

    dim3 sgrid(NCHUNK, BB);                  // (256, 4)
    scan_passC<<<sgrid, 256>>>(out);
}